// round 1
// baseline (speedup 1.0000x reference)
#include <cuda_runtime.h>
#include <math.h>

// Problem constants: B=32, S=512, H=128.
// Restructured as one GEMM: M = 4*B*S = 65536 rows (block j major), N = 512, K = 512.
//   K chunks of 128: [CNN_j | gaz(j even? fwd:back) | global_matrix | exper_input]
//   N cols: [0,128) = new_state pre (tanh), [128,512) = 3 gate groups (sigmoid+softmax)
//   Weight: k<384 -> W_cat[k][j*512+n]; k>=384 -> (n>=128 ? W_exp[k-384][j*384+n-128] : 0)

namespace {
constexpr int Hh = 128;
constexpr int Bsz = 32;
constexpr int Ssz = 512;
constexpr int BM = 64;          // rows per CTA
constexpr int KC = 16;          // K-slice per stage
constexpr int SA_STRIDE = 20;   // padded A row stride (floats), keeps float4 alignment
constexpr int SMEM_FLOATS = 2 * KC * 512 + 2 * BM * SA_STRIDE;  // 18944 floats = 75776 B
}

__device__ __forceinline__ float sigmoidf_(float x) {
    return 1.0f / (1.0f + __expf(-x));
}

__global__ void __launch_bounds__(256, 1)
layergate_fused(const float* __restrict__ cnn,
                const float* __restrict__ gaz,
                const float* __restrict__ gazb,
                const float* __restrict__ gm,
                const float* __restrict__ expi,
                const float* __restrict__ Wcat,
                const float* __restrict__ bcat,
                const float* __restrict__ Wexp,
                const float* __restrict__ bexp,
                float* __restrict__ out)
{
    extern __shared__ float smem[];
    float* sB = smem;                    // [2][KC][512]
    float* sA = smem + 2 * KC * 512;     // [2][BM][SA_STRIDE]

    const int tid = threadIdx.x;
    const int tx = tid & 31;             // 32 thread-cols: h = tx*4 .. tx*4+3
    const int ty = tid >> 5;             // 8 thread-rows: rows ty*8 .. ty*8+7

    const int r0 = blockIdx.x * BM;      // global row base
    const int j  = r0 >> 14;             // r0 / (B*S) = /16384
    const int b  = (r0 >> 9) & 31;       // (r0/S) % B
    const int s0 = r0 & 511;             // r0 % S   (64 | 512, so one (j,b) per CTA)

    // ---- global A-load mapping: thread loads one float4 (row = tid/4, k4 = tid%4)
    const int la_row = tid >> 2;
    const int la_k4  = tid & 3;
    const int sAbsL  = s0 + la_row;
    const float* ap0 = cnn  + (size_t)(b * (4 * Ssz) + j * Ssz + sAbsL) * Hh;
    const float* ap1 = ((j & 1) ? gazb : gaz) + (size_t)(b * Ssz + sAbsL) * Hh;
    const float* ap2 = gm   + (size_t)(b * Ssz + sAbsL) * Hh;
    const float* ap3 = expi + (size_t)(b * Ssz + sAbsL) * Hh;

    // ---- global B-load mapping: 8 float4 per thread (n4 = tid%128, kk = tid/128 + 2q)
    const int lb_n4 = tid & 127;
    const int lb_k0 = tid >> 7;          // uniform within a warp
    const int nB = lb_n4 * 4;

    float4 pa;
    float4 pb[8];

    auto loadTile = [&](int kt) {
        int kg = kt * KC + la_k4 * 4;
        int chunk = kg >> 7;
        int koff  = kg & 127;
        const float* p = ap0;
        if (chunk == 1) p = ap1;
        if (chunk == 2) p = ap2;
        if (chunk == 3) p = ap3;
        pa = *reinterpret_cast<const float4*>(p + koff);
#pragma unroll
        for (int q = 0; q < 8; q++) {
            int kglob = kt * KC + lb_k0 + 2 * q;
            float4 w;
            if (kglob < 384) {
                w = *reinterpret_cast<const float4*>(
                        Wcat + (size_t)kglob * 2048 + j * 512 + nB);
            } else if (nB >= 128) {
                w = *reinterpret_cast<const float4*>(
                        Wexp + (size_t)(kglob - 384) * 1536 + j * 384 + (nB - 128));
            } else {
                w = make_float4(0.f, 0.f, 0.f, 0.f);
            }
            pb[q] = w;
        }
    };

    auto storeTile = [&](int buf) {
        *reinterpret_cast<float4*>(
            sA + buf * (BM * SA_STRIDE) + la_row * SA_STRIDE + la_k4 * 4) = pa;
        float* bs = sB + buf * (KC * 512);
#pragma unroll
        for (int q = 0; q < 8; q++) {
            *reinterpret_cast<float4*>(bs + (lb_k0 + 2 * q) * 512 + nB) = pb[q];
        }
    };

    float acc[8][16];                    // [row i][c = jj*4 + v]
#pragma unroll
    for (int i = 0; i < 8; i++)
#pragma unroll
        for (int c = 0; c < 16; c++) acc[i][c] = 0.f;

    loadTile(0);
    storeTile(0);
    __syncthreads();

    for (int kt = 0; kt < 32; kt++) {
        const int buf = kt & 1;
        if (kt < 31) loadTile(kt + 1);   // prefetch next slice into regs

        const float* bA = sA + buf * (BM * SA_STRIDE) + (ty * 8) * SA_STRIDE;
        const float* bB = sB + buf * (KC * 512) + tx * 4;
#pragma unroll
        for (int kk = 0; kk < KC; kk++) {
            float a[8];
#pragma unroll
            for (int i = 0; i < 8; i++) a[i] = bA[i * SA_STRIDE + kk];
            float bv[16];
#pragma unroll
            for (int jj = 0; jj < 4; jj++) {
                float4 t = *reinterpret_cast<const float4*>(bB + kk * 512 + jj * 128);
                bv[jj * 4 + 0] = t.x; bv[jj * 4 + 1] = t.y;
                bv[jj * 4 + 2] = t.z; bv[jj * 4 + 3] = t.w;
            }
#pragma unroll
            for (int i = 0; i < 8; i++)
#pragma unroll
                for (int c = 0; c < 16; c++)
                    acc[i][c] = fmaf(a[i], bv[c], acc[i][c]);
        }
        if (kt < 31) {
            storeTile(buf ^ 1);
            __syncthreads();
        }
    }

    // ---- epilogue: tanh / sigmoid / softmax / weighted combine, all thread-local
    const int h0 = tx * 4;
    float bC[4][4], bE[3][4];
#pragma unroll
    for (int g = 0; g < 4; g++) {
        float4 t = *reinterpret_cast<const float4*>(bcat + j * 512 + g * 128 + h0);
        bC[g][0] = t.x; bC[g][1] = t.y; bC[g][2] = t.z; bC[g][3] = t.w;
    }
#pragma unroll
    for (int g = 0; g < 3; g++) {
        float4 t = *reinterpret_cast<const float4*>(bexp + j * 384 + g * 128 + h0);
        bE[g][0] = t.x; bE[g][1] = t.y; bE[g][2] = t.z; bE[g][3] = t.w;
    }

#pragma unroll
    for (int i = 0; i < 8; i++) {
        const int row = ty * 8 + i;
        const int sAbs = s0 + row;
        float4 t1 = *reinterpret_cast<const float4*>(
            cnn + (size_t)(b * 2048 + j * 512 + sAbs) * 128 + h0);
        float4 t2 = *reinterpret_cast<const float4*>(
            expi + (size_t)(b * 512 + sAbs) * 128 + h0);
        float st1[4] = {t1.x, t1.y, t1.z, t1.w};
        float st2[4] = {t2.x, t2.y, t2.z, t2.w};
        float o[4];
#pragma unroll
        for (int v = 0; v < 4; v++) {
            float ns = tanhf(acc[i][v] + bC[0][v]);
            float g0 = sigmoidf_(acc[i][4 + v]  + bC[1][v] + bE[0][v]);
            float g1 = sigmoidf_(acc[i][8 + v]  + bC[2][v] + bE[1][v]);
            float g2 = sigmoidf_(acc[i][12 + v] + bC[3][v] + bE[2][v]);
            float e0 = __expf(g0), e1 = __expf(g1), e2 = __expf(g2);
            float inv = 1.0f / (e0 + e1 + e2);
            o[v] = (e0 * ns + e1 * st1[v] + e2 * st2[v]) * inv;
        }
        *reinterpret_cast<float4*>(out + (size_t)(r0 + row) * 128 + h0) =
            make_float4(o[0], o[1], o[2], o[3]);
    }
}

extern "C" void kernel_launch(void* const* d_in, const int* in_sizes, int n_in,
                              void* d_out, int out_size)
{
    const float* cnn  = (const float*)d_in[0];
    const float* gaz  = (const float*)d_in[1];
    const float* gazb = (const float*)d_in[2];
    const float* gm   = (const float*)d_in[3];
    const float* expi = (const float*)d_in[4];
    const float* Wcat = (const float*)d_in[5];
    const float* bcat = (const float*)d_in[6];
    const float* Wexp = (const float*)d_in[7];
    const float* bexp = (const float*)d_in[8];
    float* out = (float*)d_out;

    const int smem_bytes = SMEM_FLOATS * (int)sizeof(float);   // 75776 B
    cudaFuncSetAttribute(layergate_fused,
                         cudaFuncAttributeMaxDynamicSharedMemorySize, smem_bytes);

    const int grid = (4 * Bsz * Ssz) / BM;   // 65536 / 64 = 1024 CTAs
    layergate_fused<<<grid, 256, smem_bytes>>>(
        cnn, gaz, gazb, gm, expi, Wcat, bcat, Wexp, bexp, out);
}

// round 3
// speedup vs baseline: 1.9308x; 1.9308x over previous
#include <cuda_runtime.h>
#include <cuda_bf16.h>
#include <cstdint>
#include <math.h>

// LayerGate as one GEMM D[65536,512] = X[65536,512] @ W_aug[512,512] (per j-block),
// bf16 hi/lo split (3 HMMA terms, fp32 acc) on mma.sync.m16n8k16, fused gate epilogue.
// Weight columns reordered n' = h*4 + g so a 128-col CTA tile holds all 4 gate groups
// for 32 h values -> epilogue is CTA-local and fully coalesced.

namespace {
constexpr int STAGE_BYTES = 65536;   // per stage: A hi/lo 32KB + B hi/lo 32KB
constexpr int SMEM_TOTAL  = 131072;  // 2 stages
}

// [p][r][k] bf16, p=hi/lo, r=65536 rows, k=512 (1KB per row). 64MB per plane.
__device__ __align__(16) unsigned char g_ab[2ull * 65536 * 1024];
// [j][p][n'][k] bf16, n'=512 reordered cols, k=512. 4MB total.
__device__ __align__(16) unsigned char g_wb[4ull * 2 * 512 * 1024];

// ---------- PTX helpers (all compute_80-level: safe under .target sm_103) ----------
__device__ __forceinline__ uint32_t smem_u32(const void* p) {
    uint32_t a;
    asm("{ .reg .u64 t; cvta.to.shared.u64 t, %1; cvt.u32.u64 %0, t; }" : "=r"(a) : "l"(p));
    return a;
}
__device__ __forceinline__ void cp16(uint32_t dst, const void* src) {
    asm volatile("cp.async.cg.shared.global [%0], [%1], 16;" :: "r"(dst), "l"(src));
}
__device__ __forceinline__ void cp_commit() {
    asm volatile("cp.async.commit_group;" ::: "memory");
}
__device__ __forceinline__ void cp_wait0() {
    asm volatile("cp.async.wait_group 0;" ::: "memory");
}
__device__ __forceinline__ void ldsm4(uint32_t* r, uint32_t addr) {
    asm volatile("ldmatrix.sync.aligned.m8n8.x4.shared.b16 {%0,%1,%2,%3}, [%4];"
                 : "=r"(r[0]), "=r"(r[1]), "=r"(r[2]), "=r"(r[3]) : "r"(addr));
}
__device__ __forceinline__ void mma_bf16(float* d, const uint32_t* a, const uint32_t* b) {
    asm volatile("mma.sync.aligned.m16n8k16.row.col.f32.bf16.bf16.f32 "
                 "{%0,%1,%2,%3}, {%4,%5,%6,%7}, {%8,%9}, {%0,%1,%2,%3};"
                 : "+f"(d[0]), "+f"(d[1]), "+f"(d[2]), "+f"(d[3])
                 : "r"(a[0]), "r"(a[1]), "r"(a[2]), "r"(a[3]), "r"(b[0]), "r"(b[1]));
}

// ---------- Prep: activations -> bf16 hi/lo planes [p][r][k] ----------
__global__ void __launch_bounds__(256) wprep_a(const float* __restrict__ cnn,
                                               const float* __restrict__ gaz,
                                               const float* __restrict__ gazb,
                                               const float* __restrict__ gm,
                                               const float* __restrict__ expi)
{
    int idx = blockIdx.x * 256 + threadIdx.x;   // 8,388,608 threads
    int k4  = idx & 127;                        // k = k4*4
    int r   = idx >> 7;
    int j = r >> 14, b = (r >> 9) & 31, s = r & 511;
    int k = k4 * 4;
    int sel = k >> 7;
    const float* rp;
    if (sel == 0)      rp = cnn  + ((size_t)(b * 2048 + j * 512 + s) << 7);
    else if (sel == 1) rp = ((j & 1) ? gazb : gaz) + ((size_t)(b * 512 + s) << 7);
    else if (sel == 2) rp = gm   + ((size_t)(b * 512 + s) << 7);
    else               rp = expi + ((size_t)(b * 512 + s) << 7);
    float4 v = *reinterpret_cast<const float4*>(rp + (k & 127));
    __nv_bfloat162 h0 = __floats2bfloat162_rn(v.x, v.y);
    __nv_bfloat162 h1 = __floats2bfloat162_rn(v.z, v.w);
    __nv_bfloat162 l0 = __floats2bfloat162_rn(v.x - __bfloat162float(h0.x),
                                              v.y - __bfloat162float(h0.y));
    __nv_bfloat162 l1 = __floats2bfloat162_rn(v.z - __bfloat162float(h1.x),
                                              v.w - __bfloat162float(h1.y));
    size_t off = (size_t)r * 1024 + k4 * 8;
    *reinterpret_cast<uint2*>(g_ab + off) =
        make_uint2(*reinterpret_cast<uint32_t*>(&h0), *reinterpret_cast<uint32_t*>(&h1));
    *reinterpret_cast<uint2*>(g_ab + (64ull << 20) + off) =
        make_uint2(*reinterpret_cast<uint32_t*>(&l0), *reinterpret_cast<uint32_t*>(&l1));
}

// ---------- Prep: weights -> bf16 hi/lo planes, columns reordered n' = h*4+g ----------
__global__ void __launch_bounds__(256) wprep_w(const float* __restrict__ Wcat,
                                               const float* __restrict__ Wexp)
{
    int idx = blockIdx.x * 256 + threadIdx.x;   // 262,144 threads
    int h = idx & 127;
    int k = (idx >> 7) & 511;
    int j = idx >> 16;
#pragma unroll
    for (int g = 0; g < 4; g++) {
        float v;
        if (k < 384)     v = Wcat[(size_t)k * 2048 + j * 512 + g * 128 + h];
        else if (g >= 1) v = Wexp[(size_t)(k - 384) * 1536 + j * 384 + (g - 1) * 128 + h];
        else             v = 0.f;
        __nv_bfloat16 hb = __float2bfloat16_rn(v);
        __nv_bfloat16 lb = __float2bfloat16_rn(v - __bfloat162float(hb));
        int npr = h * 4 + g;
        size_t offHi = ((size_t)(j * 2 + 0) * 512 + npr) * 1024 + k * 2;
        size_t offLo = ((size_t)(j * 2 + 1) * 512 + npr) * 1024 + k * 2;
        *reinterpret_cast<__nv_bfloat16*>(g_wb + offHi) = hb;
        *reinterpret_cast<__nv_bfloat16*>(g_wb + offLo) = lb;
    }
}

// ---------- Main: pipelined HMMA GEMM + fused epilogue ----------
__global__ void __launch_bounds__(256, 1)
layergate_mma(const float* __restrict__ cnn,
              const float* __restrict__ expi,
              const float* __restrict__ bcat,
              const float* __restrict__ bexp,
              float* __restrict__ out)
{
    extern __shared__ __align__(1024) unsigned char smem[];
    const uint32_t sbase = smem_u32(smem);
    const int tid  = threadIdx.x;
    const int lane = tid & 31;
    const int wid  = tid >> 5;
    const int wm   = wid & 3;     // 4 warps in M
    const int wn   = wid >> 2;    // 2 warps in N
    const int mx   = blockIdx.x;  // 0..127 (row tile within j)
    const int nt   = blockIdx.y;  // 0..3   (h-block of 32)
    const int j    = blockIdx.z;  // 0..3
    const int rbase = j * 16384 + mx * 128;

    float acc[2][8][4];
#pragma unroll
    for (int mf = 0; mf < 2; mf++)
#pragma unroll
        for (int nf = 0; nf < 8; nf++)
#pragma unroll
            for (int c = 0; c < 4; c++) acc[mf][nf][c] = 0.f;

    // ---- cp.async stage loader: 16 x 16B per thread (A hi/lo 32KB + B hi/lo 32KB)
    auto issue_stage = [&](int s) {
        const uint32_t dstStage = sbase + (s & 1) * STAGE_BYTES;
#pragma unroll
        for (int i = 0; i < 8; i++) {
            int c = i * 256 + tid;                 // 2048 A chunks
            int p = c >> 10, r = (c >> 3) & 127, ch = c & 7;
            const unsigned char* src = g_ab + (size_t)p * (64ull << 20)
                                     + (size_t)(rbase + r) * 1024 + s * 128 + ch * 16;
            cp16(dstStage + p * 16384 + r * 128 + ((ch ^ (r & 7)) * 16), src);
        }
#pragma unroll
        for (int i = 0; i < 8; i++) {
            int c = i * 256 + tid;                 // 2048 B chunks
            int p = c >> 10, r = (c >> 3) & 127, ch = c & 7;
            const unsigned char* src = g_wb
                + ((size_t)(j * 2 + p) * 512 + nt * 128 + r) * 1024 + s * 128 + ch * 16;
            cp16(dstStage + 32768 + p * 16384 + r * 128 + ((ch ^ (r & 7)) * 16), src);
        }
        cp_commit();
    };

    // ldmatrix lane geometry
    const int arow = lane & 15;                 // A: rows, lanes 0-15 chunk0, 16-31 chunk1
    const int ac   = lane >> 4;
    const int brow = (lane & 7) | ((lane >> 4) << 3);  // B: n rows
    const int bc   = (lane >> 3) & 1;

    auto compute_stage = [&](int s) {
        const uint32_t st = sbase + (s & 1) * STAGE_BYTES;
        const uint32_t aBase = st + (wm * 32 + arow) * 128;
        const uint32_t bBase = st + 32768 + (wn * 64 + brow) * 128;
#pragma unroll
        for (int kk = 0; kk < 4; kk++) {
            const uint32_t aoff = ((kk * 2 + ac) ^ (arow & 7)) * 16;
            const uint32_t boff = ((kk * 2 + bc) ^ (brow & 7)) * 16;
            uint32_t Ahi[2][4], Alo[2][4];
#pragma unroll
            for (int mf = 0; mf < 2; mf++) {
                ldsm4(Ahi[mf], aBase + mf * 2048 + aoff);
                ldsm4(Alo[mf], aBase + 16384 + mf * 2048 + aoff);
            }
            uint32_t Bhi[8][2], Blo[8][2];
#pragma unroll
            for (int ng = 0; ng < 4; ng++) {
                uint32_t t[4];
                ldsm4(t, bBase + ng * 2048 + boff);
                Bhi[2 * ng][0] = t[0]; Bhi[2 * ng][1] = t[1];
                Bhi[2 * ng + 1][0] = t[2]; Bhi[2 * ng + 1][1] = t[3];
                ldsm4(t, bBase + 16384 + ng * 2048 + boff);
                Blo[2 * ng][0] = t[0]; Blo[2 * ng][1] = t[1];
                Blo[2 * ng + 1][0] = t[2]; Blo[2 * ng + 1][1] = t[3];
            }
#pragma unroll
            for (int mf = 0; mf < 2; mf++)
#pragma unroll
                for (int nf = 0; nf < 8; nf++) {
                    mma_bf16(acc[mf][nf], Ahi[mf], Bhi[nf]);
                    mma_bf16(acc[mf][nf], Alo[mf], Bhi[nf]);
                    mma_bf16(acc[mf][nf], Ahi[mf], Blo[nf]);
                }
        }
    };

    issue_stage(0);
    for (int s = 0; s < 8; s++) {
        cp_wait0();
        __syncthreads();
        if (s < 7) issue_stage(s + 1);
        compute_stage(s);
    }

    // ---- Epilogue phase 1: dump acc to smem gate tile [128 rows][128 n'] fp32 (buffer 0)
    float* gate = reinterpret_cast<float*>(smem);
    const int gid = lane >> 2, tig = lane & 3;
#pragma unroll
    for (int mf = 0; mf < 2; mf++)
#pragma unroll
        for (int nf = 0; nf < 8; nf++) {
            int row = wm * 32 + mf * 16 + gid;
            int col = wn * 64 + nf * 8 + tig * 2;
            *reinterpret_cast<float2*>(gate + row * 128 + col) =
                make_float2(acc[mf][nf][0], acc[mf][nf][1]);
            *reinterpret_cast<float2*>(gate + (row + 8) * 128 + col) =
                make_float2(acc[mf][nf][2], acc[mf][nf][3]);
        }
    __syncthreads();

    // ---- Epilogue phase 2: per (row, h) gather float4 {ns,g1,g2,g3}, finish, store
    const int hl = lane;                 // 0..31
    const int hg = nt * 32 + hl;
    const float bc0 = bcat[j * 512 + hg];
    const float bc1 = bcat[j * 512 + 128 + hg];
    const float bc2 = bcat[j * 512 + 256 + hg];
    const float bc3 = bcat[j * 512 + 384 + hg];
    const float be1 = bexp[j * 384 + hg];
    const float be2 = bexp[j * 384 + 128 + hg];
    const float be3 = bexp[j * 384 + 256 + hg];
#pragma unroll
    for (int i = 0; i < 16; i++) {
        const int row = wid * 16 + i;
        const int r = rbase + row;
        const int bb = (r >> 9) & 31, ss = r & 511;
        float4 gv = *reinterpret_cast<const float4*>(gate + row * 128 + hl * 4);
        float s1 = cnn[((size_t)(bb * 2048 + j * 512 + ss) << 7) + hg];
        float s2 = expi[((size_t)(bb * 512 + ss) << 7) + hg];
        float ns = tanhf(gv.x + bc0);
        float g1 = 1.f / (1.f + __expf(-(gv.y + bc1 + be1)));
        float g2 = 1.f / (1.f + __expf(-(gv.z + bc2 + be2)));
        float g3 = 1.f / (1.f + __expf(-(gv.w + bc3 + be3)));
        float e1 = __expf(g1), e2 = __expf(g2), e3 = __expf(g3);
        float inv = 1.f / (e1 + e2 + e3);
        out[((size_t)r << 7) + hg] = (e1 * ns + e2 * s1 + e3 * s2) * inv;
    }
}

extern "C" void kernel_launch(void* const* d_in, const int* in_sizes, int n_in,
                              void* d_out, int out_size)
{
    const float* cnn  = (const float*)d_in[0];
    const float* gaz  = (const float*)d_in[1];
    const float* gazb = (const float*)d_in[2];
    const float* gm   = (const float*)d_in[3];
    const float* expi = (const float*)d_in[4];
    const float* Wcat = (const float*)d_in[5];
    const float* bcat = (const float*)d_in[6];
    const float* Wexp = (const float*)d_in[7];
    const float* bexp = (const float*)d_in[8];
    float* out = (float*)d_out;

    wprep_a<<<32768, 256>>>(cnn, gaz, gazb, gm, expi);
    wprep_w<<<1024, 256>>>(Wcat, Wexp);

    cudaFuncSetAttribute(layergate_mma,
                         cudaFuncAttributeMaxDynamicSharedMemorySize, SMEM_TOTAL);
    layergate_mma<<<dim3(128, 4, 4), 256, SMEM_TOTAL>>>(cnn, expi, bcat, bexp, out);
}

// round 6
// speedup vs baseline: 4.4296x; 2.2941x over previous
#include <cuda_runtime.h>
#include <cuda_fp16.h>
#include <cstdint>
#include <math.h>

// LayerGate as one GEMM D[65536,512] = X[65536,512] @ W_aug[512,512] (per j-block),
// fp16 single-pass mma.sync.m16n8k16 (fp32 acc), fused gate epilogue.
// Weight columns reordered n' = h*4 + g so a 128-col CTA tile holds all 4 gate groups.

namespace {
constexpr int STAGE_BYTES = 32768;   // per stage: A 16KB + B 16KB
constexpr int SMEM_TOTAL  = 65536;   // 2 stages (also reused as 128x128 fp32 gate tile)
}

// [r][k] fp16, 65536 rows x 512 k = 64MB (fits L2)
__device__ __align__(16) unsigned char g_ah[65536ull * 1024];
// [j][n'][k] fp16, n'=512 reordered cols = 2MB
__device__ __align__(16) unsigned char g_wh[4ull * 512 * 1024];

// ---------- PTX helpers (compute_80-level; safe under .target sm_103) ----------
__device__ __forceinline__ uint32_t smem_u32(const void* p) {
    uint32_t a;
    asm("{ .reg .u64 t; cvta.to.shared.u64 t, %1; cvt.u32.u64 %0, t; }" : "=r"(a) : "l"(p));
    return a;
}
__device__ __forceinline__ void cp16(uint32_t dst, const void* src) {
    asm volatile("cp.async.cg.shared.global [%0], [%1], 16;" :: "r"(dst), "l"(src));
}
__device__ __forceinline__ void cp_commit() {
    asm volatile("cp.async.commit_group;" ::: "memory");
}
__device__ __forceinline__ void cp_wait0() {
    asm volatile("cp.async.wait_group 0;" ::: "memory");
}
__device__ __forceinline__ void ldsm4(uint32_t* r, uint32_t addr) {
    asm volatile("ldmatrix.sync.aligned.m8n8.x4.shared.b16 {%0,%1,%2,%3}, [%4];"
                 : "=r"(r[0]), "=r"(r[1]), "=r"(r[2]), "=r"(r[3]) : "r"(addr));
}
__device__ __forceinline__ void mma_fp16(float* d, const uint32_t* a, const uint32_t* b) {
    asm volatile("mma.sync.aligned.m16n8k16.row.col.f32.f16.f16.f32 "
                 "{%0,%1,%2,%3}, {%4,%5,%6,%7}, {%8,%9}, {%0,%1,%2,%3};"
                 : "+f"(d[0]), "+f"(d[1]), "+f"(d[2]), "+f"(d[3])
                 : "r"(a[0]), "r"(a[1]), "r"(a[2]), "r"(a[3]), "r"(b[0]), "r"(b[1]));
}

// ---------- Prep: activations -> fp16 plane [r][k] ----------
__global__ void __launch_bounds__(256) wprep_a(const float* __restrict__ cnn,
                                               const float* __restrict__ gaz,
                                               const float* __restrict__ gazb,
                                               const float* __restrict__ gm,
                                               const float* __restrict__ expi)
{
    int idx = blockIdx.x * 256 + threadIdx.x;   // 8,388,608 threads
    int k4  = idx & 127;                        // k = k4*4
    int r   = idx >> 7;
    int j = r >> 14, b = (r >> 9) & 31, s = r & 511;
    int k = k4 * 4;
    int sel = k >> 7;
    const float* rp;
    if (sel == 0)      rp = cnn  + ((size_t)(b * 2048 + j * 512 + s) << 7);
    else if (sel == 1) rp = ((j & 1) ? gazb : gaz) + ((size_t)(b * 512 + s) << 7);
    else if (sel == 2) rp = gm   + ((size_t)(b * 512 + s) << 7);
    else               rp = expi + ((size_t)(b * 512 + s) << 7);
    float4 v = *reinterpret_cast<const float4*>(rp + (k & 127));
    __half2 h0 = __floats2half2_rn(v.x, v.y);
    __half2 h1 = __floats2half2_rn(v.z, v.w);
    *reinterpret_cast<uint2*>(g_ah + (size_t)r * 1024 + k4 * 8) =
        make_uint2(*reinterpret_cast<uint32_t*>(&h0), *reinterpret_cast<uint32_t*>(&h1));
}

// ---------- Prep: weights -> fp16 plane, columns reordered n' = h*4+g ----------
__global__ void __launch_bounds__(256) wprep_w(const float* __restrict__ Wcat,
                                               const float* __restrict__ Wexp)
{
    int idx = blockIdx.x * 256 + threadIdx.x;   // 262,144 threads
    int h = idx & 127;
    int k = (idx >> 7) & 511;
    int j = idx >> 16;
#pragma unroll
    for (int g = 0; g < 4; g++) {
        float v;
        if (k < 384)     v = Wcat[(size_t)k * 2048 + j * 512 + g * 128 + h];
        else if (g >= 1) v = Wexp[(size_t)(k - 384) * 1536 + j * 384 + (g - 1) * 128 + h];
        else             v = 0.f;
        int npr = h * 4 + g;
        *reinterpret_cast<__half*>(g_wh + ((size_t)(j * 512) + npr) * 1024 + k * 2) =
            __float2half_rn(v);
    }
}

// ---------- Main: pipelined fp16 HMMA GEMM + fused epilogue ----------
__global__ void __launch_bounds__(256, 2)
layergate_mma(const float* __restrict__ cnn,
              const float* __restrict__ expi,
              const float* __restrict__ bcat,
              const float* __restrict__ bexp,
              float* __restrict__ out)
{
    extern __shared__ __align__(1024) unsigned char smem[];
    const uint32_t sbase = smem_u32(smem);
    const int tid  = threadIdx.x;
    const int lane = tid & 31;
    const int wid  = tid >> 5;
    const int wm   = wid & 3;     // 4 warps in M
    const int wn   = wid >> 2;    // 2 warps in N
    const int nt   = blockIdx.x;  // 0..3   (h-block of 32) — fastest => A tile L2-shared
    const int mx   = blockIdx.y;  // 0..127 (row tile within j)
    const int j    = blockIdx.z;  // 0..3
    const int rbase = j * 16384 + mx * 128;

    float acc[2][8][4];
#pragma unroll
    for (int mf = 0; mf < 2; mf++)
#pragma unroll
        for (int nf = 0; nf < 8; nf++)
#pragma unroll
            for (int c = 0; c < 4; c++) acc[mf][nf][c] = 0.f;

    // ---- cp.async stage loader: 8 x 16B per thread (A 16KB + B 16KB)
    auto issue_stage = [&](int s) {
        const uint32_t dstStage = sbase + (s & 1) * STAGE_BYTES;
#pragma unroll
        for (int i = 0; i < 4; i++) {
            int c = i * 256 + tid;                 // 1024 A chunks
            int r = c >> 3, ch = c & 7;
            const unsigned char* src =
                g_ah + (size_t)(rbase + r) * 1024 + s * 128 + ch * 16;
            cp16(dstStage + r * 128 + ((ch ^ (r & 7)) * 16), src);
        }
#pragma unroll
        for (int i = 0; i < 4; i++) {
            int c = i * 256 + tid;                 // 1024 B chunks
            int r = c >> 3, ch = c & 7;
            const unsigned char* src =
                g_wh + ((size_t)(j * 512) + nt * 128 + r) * 1024 + s * 128 + ch * 16;
            cp16(dstStage + 16384 + r * 128 + ((ch ^ (r & 7)) * 16), src);
        }
        cp_commit();
    };

    // ldmatrix lane geometry
    const int arow = lane & 15;
    const int ac   = lane >> 4;
    const int brow = (lane & 7) | ((lane >> 4) << 3);
    const int bc   = (lane >> 3) & 1;

    auto compute_stage = [&](int s) {
        const uint32_t st = sbase + (s & 1) * STAGE_BYTES;
        const uint32_t aBase = st + (wm * 32 + arow) * 128;
        const uint32_t bBase = st + 16384 + (wn * 64 + brow) * 128;
#pragma unroll
        for (int kk = 0; kk < 4; kk++) {
            const uint32_t aoff = ((kk * 2 + ac) ^ (arow & 7)) * 16;
            const uint32_t boff = ((kk * 2 + bc) ^ (brow & 7)) * 16;
            uint32_t A[2][4];
#pragma unroll
            for (int mf = 0; mf < 2; mf++) ldsm4(A[mf], aBase + mf * 2048 + aoff);
            uint32_t B[8][2];
#pragma unroll
            for (int ng = 0; ng < 4; ng++) {
                uint32_t t[4];
                ldsm4(t, bBase + ng * 2048 + boff);
                B[2 * ng][0] = t[0]; B[2 * ng][1] = t[1];
                B[2 * ng + 1][0] = t[2]; B[2 * ng + 1][1] = t[3];
            }
#pragma unroll
            for (int mf = 0; mf < 2; mf++)
#pragma unroll
                for (int nf = 0; nf < 8; nf++)
                    mma_fp16(acc[mf][nf], A[mf], B[nf]);
        }
    };

    issue_stage(0);
    for (int s = 0; s < 8; s++) {
        cp_wait0();
        __syncthreads();
        if (s < 7) issue_stage(s + 1);
        compute_stage(s);
    }

    // ---- Epilogue phase 1: dump acc to smem gate tile [128 rows][128 n'] fp32
    __syncthreads();
    float* gate = reinterpret_cast<float*>(smem);
    const int gid = lane >> 2, tig = lane & 3;
#pragma unroll
    for (int mf = 0; mf < 2; mf++)
#pragma unroll
        for (int nf = 0; nf < 8; nf++) {
            int row = wm * 32 + mf * 16 + gid;
            int col = wn * 64 + nf * 8 + tig * 2;
            *reinterpret_cast<float2*>(gate + row * 128 + col) =
                make_float2(acc[mf][nf][0], acc[mf][nf][1]);
            *reinterpret_cast<float2*>(gate + (row + 8) * 128 + col) =
                make_float2(acc[mf][nf][2], acc[mf][nf][3]);
        }
    __syncthreads();

    // ---- Epilogue phase 2: per (row, h) gather float4 {ns,g1,g2,g3}, finish, store
    const int hl = lane;
    const int hg = nt * 32 + hl;
    const float bc0 = bcat[j * 512 + hg];
    const float bc1 = bcat[j * 512 + 128 + hg];
    const float bc2 = bcat[j * 512 + 256 + hg];
    const float bc3 = bcat[j * 512 + 384 + hg];
    const float be1 = bexp[j * 384 + hg];
    const float be2 = bexp[j * 384 + 128 + hg];
    const float be3 = bexp[j * 384 + 256 + hg];
#pragma unroll
    for (int i = 0; i < 16; i++) {
        const int row = wid * 16 + i;
        const int r = rbase + row;
        const int bb = (r >> 9) & 31, ss = r & 511;
        float4 gv = *reinterpret_cast<const float4*>(gate + row * 128 + hl * 4);
        float s1 = cnn[((size_t)(bb * 2048 + j * 512 + ss) << 7) + hg];
        float s2 = expi[((size_t)(bb * 512 + ss) << 7) + hg];
        float ns = tanhf(gv.x + bc0);
        float g1 = 1.f / (1.f + __expf(-(gv.y + bc1 + be1)));
        float g2 = 1.f / (1.f + __expf(-(gv.z + bc2 + be2)));
        float g3 = 1.f / (1.f + __expf(-(gv.w + bc3 + be3)));
        float e1 = __expf(g1), e2 = __expf(g2), e3 = __expf(g3);
        float inv = 1.f / (e1 + e2 + e3);
        out[((size_t)r << 7) + hg] = (e1 * ns + e2 * s1 + e3 * s2) * inv;
    }
}

extern "C" void kernel_launch(void* const* d_in, const int* in_sizes, int n_in,
                              void* d_out, int out_size)
{
    const float* cnn  = (const float*)d_in[0];
    const float* gaz  = (const float*)d_in[1];
    const float* gazb = (const float*)d_in[2];
    const float* gm   = (const float*)d_in[3];
    const float* expi = (const float*)d_in[4];
    const float* Wcat = (const float*)d_in[5];
    const float* bcat = (const float*)d_in[6];
    const float* Wexp = (const float*)d_in[7];
    const float* bexp = (const float*)d_in[8];
    float* out = (float*)d_out;

    wprep_a<<<32768, 256>>>(cnn, gaz, gazb, gm, expi);
    wprep_w<<<1024, 256>>>(Wcat, Wexp);

    cudaFuncSetAttribute(layergate_mma,
                         cudaFuncAttributeMaxDynamicSharedMemorySize, SMEM_TOTAL);
    layergate_mma<<<dim3(4, 128, 4), 256, SMEM_TOTAL>>>(cnn, expi, bcat, bexp, out);
}